// round 16
// baseline (speedup 1.0000x reference)
#include <cuda_runtime.h>
#include <cstdint>

// EMA scan: sta_t = 0.4*sta_{t-1} + 0.6*x_t  (a = 0.4, a^16 ~ 4.3e-7 -> 16-step warm-up)
// 64-thread blocks, 1 row-chunk each (9.4 KB tile) -> ~23 independent phase-streams/SM.

#define T_LEN   6000
#define CH      3
#define ROW_F   (T_LEN * CH)            // 18000 floats per batch row
#define WARM    16                      // warm-up steps (a^16 ~ 4.3e-7)
#define SEG     12                      // per-thread segment (36-float stride: conflict-free fl4 banks)
#define SEGS    64                      // segments per chunk = threads per block
#define S_CHUNK (SEG * SEGS)            // 768 timesteps per chunk
#define THREADS SEGS                    // 64
#define TILE_T  (WARM + S_CHUNK)        // 784
#define TILE_F  (TILE_T * CH)           // 2352 floats = 9408 B
#define TILE_Q  (TILE_F / 4)            // 588 quads
#define OUT_Q   (S_CHUNK * CH / 4)      // 576 quads
#define N_CHUNKS 8                      // covers 6144; tail guarded
#define W_A     0.4f
#define W_W     0.6f

// one EMA step over 3 channels
#define STEP(X0, X1, X2)                         \
    c0 = fmaf(W_A, c0, W_W * (X0));              \
    c1 = fmaf(W_A, c1, W_W * (X1));              \
    c2 = fmaf(W_A, c2, W_W * (X2));

__global__ __launch_bounds__(THREADS)
void ema_scan_kernel(const float* __restrict__ in, float* __restrict__ out) {
    __shared__ float4 tile4[TILE_Q];               // 9408 B
    float* tile = reinterpret_cast<float*>(tile4);

    const int tid   = threadIdx.x;
    const int chunk = blockIdx.x & (N_CHUNKS - 1);
    const int row   = blockIdx.x >> 3;
    const int cs    = chunk * S_CHUNK;             // chunk start timestep
    const int gbase = cs * CH - WARM * CH;         // float offset of tile start (mult of 4)

    const float* rowin = in + (size_t)row * ROW_F;

    // ---- stage GMEM -> SMEM via cp.async (zero-fill for OOB quads) ----
    // OOB-low -> zeros == true zero init state; OOB-high only in tail chunk (outputs guarded).
    {
        const uint32_t sbase = (uint32_t)__cvta_generic_to_shared(tile);
        #pragma unroll
        for (int it = 0; it < 10; it++) {
            int q = tid + it * THREADS;
            if (q < TILE_Q) {
                int g  = gbase + q * 4;
                int gc = g < 0 ? 0 : (g > ROW_F - 4 ? ROW_F - 4 : g);
                int sz = (g >= 0 && g <= ROW_F - 4) ? 16 : 0;      // 0 => full zero-fill
                asm volatile("cp.async.cg.shared.global [%0], [%1], 16, %2;\n"
                             :: "r"(sbase + (uint32_t)q * 16), "l"(rowin + gc), "r"(sz));
            }
        }
        asm volatile("cp.async.commit_group;\n");
        asm volatile("cp.async.wait_group 0;\n");
    }
    __syncthreads();

    float c0 = 0.f, c1 = 0.f, c2 = 0.f;

    // ---- phase 1: warm-up carry, float4 reads (16 steps = 12 quads, reads only) ----
    {
        const float4* wp = reinterpret_cast<const float4*>(tile + tid * (SEG * CH)); // 36-float stride
        #pragma unroll
        for (int g3 = 0; g3 < WARM / 4; g3++) {    // 4 groups of 3 quads = 4 steps each
            float4 q0 = wp[3 * g3 + 0];
            float4 q1 = wp[3 * g3 + 1];
            float4 q2 = wp[3 * g3 + 2];
            STEP(q0.x, q0.y, q0.z)
            STEP(q0.w, q1.x, q1.y)
            STEP(q1.z, q1.w, q2.x)
            STEP(q2.y, q2.z, q2.w)
        }
    }
    __syncthreads();   // all warm-up reads complete before in-place overwrite

    // ---- phase 2: in-place segment scan, float4 (12 steps = 9 quads) ----
    {
        float4* sp = reinterpret_cast<float4*>(tile + WARM * CH + tid * (SEG * CH));
        #pragma unroll
        for (int g3 = 0; g3 < SEG / 4; g3++) {
            float4 q0 = sp[3 * g3 + 0];
            float4 q1 = sp[3 * g3 + 1];
            float4 q2 = sp[3 * g3 + 2];
            STEP(q0.x, q0.y, q0.z)  q0.x = c0; q0.y = c1; q0.z = c2;
            STEP(q0.w, q1.x, q1.y)  q0.w = c0; q1.x = c1; q1.y = c2;
            STEP(q1.z, q1.w, q2.x)  q1.z = c0; q1.w = c1; q2.x = c2;
            STEP(q2.y, q2.z, q2.w)  q2.y = c0; q2.z = c1; q2.w = c2;
            sp[3 * g3 + 0] = q0;
            sp[3 * g3 + 1] = q1;
            sp[3 * g3 + 2] = q2;
        }
    }
    __syncthreads();

    // ---- coalesced float4 store: SMEM chunk region -> GMEM (576 quads = 9 exact iters) ----
    {
        const int obase = cs * CH;
        float* rowout = out + (size_t)row * ROW_F;
        const float* src = tile + WARM * CH;
        #pragma unroll
        for (int it = 0; it < 9; it++) {
            int q = tid + it * THREADS;
            int g = obase + q * 4;
            if (g < ROW_F)
                *reinterpret_cast<float4*>(rowout + g) =
                    *reinterpret_cast<const float4*>(src + q * 4);
        }
    }
}

extern "C" void kernel_launch(void* const* d_in, const int* in_sizes, int n_in,
                              void* d_out, int out_size) {
    const float* wave = (const float*)d_in[0];
    float* out = (float*)d_out;
    const int B = in_sizes[0] / ROW_F;             // 4096
    const int blocks = B * N_CHUNKS;               // 32768
    ema_scan_kernel<<<blocks, THREADS>>>(wave, out);
}